// round 8
// baseline (speedup 1.0000x reference)
#include <cuda_runtime.h>
#include <cuda_bf16.h>
#include <cstdint>

// Problem constants (fixed by the dataset)
#define B_DIM 32
#define L_DIM 256
#define H_DIM 512
#define H4    (H_DIM / 4)      // 128 float4 per row
#define FPB   16               // frames per block
#define KPT   8                // consecutive frames per thread

// ---------------------------------------------------------------------------
// Single fused frame-major kernel, register-level row dedup.
// grid = (ceil(T/FPB), B), 256 threads.
//  1. Redundant per-block scan of batch b's 256 durations (L2-resident, 1KB).
//  2. Interval-overlap scatter: source index per frame into s_rows[FPB]
//     (-1 = masked tail frame).
//  3. Each thread owns column c and 8 CONSECUTIVE frames (fsub group).
//     Rows are non-decreasing -> ~2 unique rows per thread: load only on
//     row change (predicated, warp-uniform), else reuse the register value.
//  4. 8 coalesced STG.128 per thread + 16 mask floats.
// ---------------------------------------------------------------------------
__global__ void __launch_bounds__(256, 4)
k_fused(const float4* __restrict__ x4,
        const int*    __restrict__ dur,
        float4*       __restrict__ out4,
        float*        __restrict__ mask_out,
        int T) {
    const int b    = blockIdx.y;
    const int t0   = blockIdx.x * FPB;
    const int tid  = threadIdx.x;         // 0..255
    const int lane = tid & 31;
    const int wid  = tid >> 5;            // 0..7

    __shared__ int s_warp[8];
    __shared__ int s_rows[FPB];           // source index per frame (-1 = tail)

    if (tid < FPB) s_rows[tid] = -1;

    // ---- scan of the 256 durations of batch b (1 per thread) ----
    const int d = __ldg(&dur[b * L_DIM + tid]);
    int v = d;
    #pragma unroll
    for (int off = 1; off < 32; off <<= 1) {
        int n = __shfl_up_sync(0xffffffffu, v, off);
        if (lane >= off) v += n;
    }
    if (lane == 31) s_warp[wid] = v;
    __syncthreads();
    if (wid == 0) {
        int w = (lane < 8) ? s_warp[lane] : 0;
        #pragma unroll
        for (int off = 1; off < 8; off <<= 1) {
            int n = __shfl_up_sync(0xffffffffu, w, off);
            if (lane >= off) w += n;
        }
        if (lane < 8) s_warp[lane] = w;
    }
    __syncthreads();

    const int incl  = v + ((wid > 0) ? s_warp[wid - 1] : 0);
    const int start = incl - d;

    // ---- scatter: mark frames in [t0, t0+FPB) covered by this thread ----
    {
        int lo = start > t0 ? start : t0;
        int hi = incl < t0 + FPB ? incl : t0 + FPB;
        for (int t = lo; t < hi; ++t)
            s_rows[t - t0] = tid;          // source position within batch
    }
    __syncthreads();

    // ---- per-thread frame rows (two broadcast LDS.128) ----
    const int c    = tid & (H4 - 1);
    const int fsub = tid >> 7;             // 0 or 1: frame group [0..7] / [8..15]
    const int4* sr4 = (const int4*)s_rows;
    const int4 ra = sr4[fsub * 2];
    const int4 rb = sr4[fsub * 2 + 1];
    int r[KPT] = { ra.x, ra.y, ra.z, ra.w, rb.x, rb.y, rb.z, rb.w };

    // ---- gather with register dedup (r is warp-uniform: no divergence) ----
    const float4* xb = x4 + (size_t)b * L_DIM * H4 + c;
    const float4 z4 = make_float4(0.f, 0.f, 0.f, 0.f);
    float4 vv[KPT];
    #pragma unroll
    for (int k = 0; k < KPT; ++k) {
        if (k == 0 || r[k] != r[k - 1])
            vv[k] = (r[k] >= 0) ? __ldg(xb + (size_t)r[k] * H4) : z4;
        else
            vv[k] = vv[k - 1];
    }

    // ---- stores: 8 consecutive frames, warp writes 512B per frame ----
    float4* ob = out4 + ((size_t)b * T + t0 + fsub * KPT) * H4 + c;
    #pragma unroll
    for (int k = 0; k < KPT; ++k) {
        if (t0 + fsub * KPT + k < T)
            ob[(size_t)k * H4] = vv[k];
    }

    // ---- mask ----
    if (tid < FPB) {
        const int t = t0 + tid;
        if (t < T)
            mask_out[(size_t)b * T + t] = (s_rows[tid] >= 0) ? 1.0f : 0.0f;
    }
}

// ---------------------------------------------------------------------------
extern "C" void kernel_launch(void* const* d_in, const int* in_sizes, int n_in,
                              void* d_out, int out_size) {
    const float* x   = (const float*)d_in[0];   // (B, L, H) float32
    const int*   dur = (const int*)d_in[1];     // (B, L)    int32

    // out_size = B*T*(H+1)  =>  T
    const int T = out_size / (B_DIM * (H_DIM + 1));

    float* out      = (float*)d_out;                          // (B, T, H)
    float* mask_out = out + (size_t)B_DIM * T * H_DIM;        // (B, T)

    dim3 grid((T + FPB - 1) / FPB, B_DIM);
    k_fused<<<grid, 256>>>((const float4*)x, dur, (float4*)out, mask_out, T);

    (void)in_sizes; (void)n_in;
}

// round 10
// speedup vs baseline: 1.2561x; 1.2561x over previous
#include <cuda_runtime.h>
#include <cuda_bf16.h>
#include <cstdint>

// Problem constants (fixed by the dataset)
#define B_DIM 32
#define L_DIM 256
#define H_DIM 512
#define H4    (H_DIM / 4)      // 128 float4 per row
#define FPB   32               // frames per block
#define KPT   8                // consecutive frames per thread
#define BLK   512              // threads per block

// ---------------------------------------------------------------------------
// Single fused frame-major kernel. grid = (ceil(T/32), B), 512 threads.
//  1. Redundant per-block scan of batch b's 256 durations (threads 0..255;
//     1KB, L2-resident, amortized over 32 frames/block).
//  2. Interval scatter: source index per frame into s_rows[32] (-1 = tail).
//  3. Thread (c = tid&127, fsub = tid>>7 in 0..3) owns 8 CONSECUTIVE frames.
//     Run-loop gather: rows non-decreasing -> reload only on row change;
//     ONE live float4 register -> low regs, high occupancy.
//  4. Evict-first (__stcs) stores: write-once stream, keep L2 clean.
// ---------------------------------------------------------------------------
__global__ void __launch_bounds__(BLK, 4)
k_fused(const float4* __restrict__ x4,
        const int*    __restrict__ dur,
        float4*       __restrict__ out4,
        float*        __restrict__ mask_out,
        int T) {
    const int b    = blockIdx.y;
    const int t0   = blockIdx.x * FPB;
    const int tid  = threadIdx.x;         // 0..511
    const int lane = tid & 31;
    const int wid  = tid >> 5;            // 0..15

    __shared__ int s_warp[8];
    __shared__ int s_rows[FPB];           // source index per frame (-1 = tail)

    if (tid < FPB) s_rows[tid] = -1;

    // ---- scan of the 256 durations of batch b (threads 0..255) ----
    int incl = 0, start = 0;
    if (tid < L_DIM) {
        const int d = __ldg(&dur[b * L_DIM + tid]);
        int v = d;
        #pragma unroll
        for (int off = 1; off < 32; off <<= 1) {
            int n = __shfl_up_sync(0xffffffffu, v, off);
            if (lane >= off) v += n;
        }
        if (lane == 31) s_warp[wid] = v;
        incl = v;
        start = v - d;                    // partial; fixed after barrier
    }
    __syncthreads();
    if (wid == 0) {
        int w = (lane < 8) ? s_warp[lane] : 0;
        #pragma unroll
        for (int off = 1; off < 8; off <<= 1) {
            int n = __shfl_up_sync(0xffffffffu, w, off);
            if (lane >= off) w += n;
        }
        if (lane < 8) s_warp[lane] = w;
    }
    __syncthreads();

    // ---- scatter: mark frames in [t0, t0+FPB) covered by this thread ----
    if (tid < L_DIM) {
        const int base = (wid > 0) ? s_warp[wid - 1] : 0;
        const int e0 = start + base;       // exclusive csum
        const int e1 = incl + base;        // inclusive csum
        int lo = e0 > t0 ? e0 : t0;
        int hi = e1 < t0 + FPB ? e1 : t0 + FPB;
        for (int t = lo; t < hi; ++t)
            s_rows[t - t0] = tid;
    }
    __syncthreads();

    // ---- per-thread rows: 8 consecutive frames via two broadcast LDS.128 ----
    const int c    = tid & (H4 - 1);
    const int fsub = tid >> 7;             // 0..3
    const int4* sr4 = (const int4*)s_rows;
    const int4 ra = sr4[fsub * 2];
    const int4 rb = sr4[fsub * 2 + 1];
    const int r[KPT] = { ra.x, ra.y, ra.z, ra.w, rb.x, rb.y, rb.z, rb.w };

    // ---- run-loop gather + streaming stores ----
    const float4* xb = x4 + (size_t)b * L_DIM * H4 + c;
    float4* ob = out4 + ((size_t)b * T + t0 + fsub * KPT) * H4 + c;
    const float4 z4 = make_float4(0.f, 0.f, 0.f, 0.f);
    const int tbase = t0 + fsub * KPT;

    float4 v = z4;
    int prev = -2;                         // forces load on first frame
    #pragma unroll
    for (int k = 0; k < KPT; ++k) {
        if (r[k] != prev) {
            v = (r[k] >= 0) ? __ldg(xb + (size_t)r[k] * H4) : z4;
            prev = r[k];
        }
        if (tbase + k < T)
            __stcs(ob + (size_t)k * H4, v);
    }

    // ---- mask ----
    if (tid < FPB) {
        const int t = t0 + tid;
        if (t < T)
            mask_out[(size_t)b * T + t] = (s_rows[tid] >= 0) ? 1.0f : 0.0f;
    }
}

// ---------------------------------------------------------------------------
extern "C" void kernel_launch(void* const* d_in, const int* in_sizes, int n_in,
                              void* d_out, int out_size) {
    const float* x   = (const float*)d_in[0];   // (B, L, H) float32
    const int*   dur = (const int*)d_in[1];     // (B, L)    int32

    // out_size = B*T*(H+1)  =>  T
    const int T = out_size / (B_DIM * (H_DIM + 1));

    float* out      = (float*)d_out;                          // (B, T, H)
    float* mask_out = out + (size_t)B_DIM * T * H_DIM;        // (B, T)

    dim3 grid((T + FPB - 1) / FPB, B_DIM);
    k_fused<<<grid, BLK>>>((const float4*)x, dur, (float4*)out, mask_out, T);

    (void)in_sizes; (void)n_in;
}